// round 12
// baseline (speedup 1.0000x reference)
#include <cuda_runtime.h>
#include <cstdint>

typedef unsigned long long ull;

#define THREADS 512
#define OUTF 11008
#define INF 4096
#define NCTA 148                    /* persistent: one CTA per SM */
#define NBLK 688                    /* OUTF/16 row-blocks */

#define SMEM_LUT_BYTES (512*16*8)   /* 64KB: LUT replicated 16x, interleaved  */
#define SMEM_TRE_BYTES (2048*16)    /* 32KB per buffer: 256 blk x 8 int4 swz  */
#define SMEM_X_BYTES   (4096*16)    /* 64KB: x staging, float4 flat, swizzled */
#define SMEM_RED_BYTES (16*128*4)   /* 8KB per buffer (two half-warp slots)   */
#define TRE_OFF  SMEM_LUT_BYTES
#define X_OFF    (TRE_OFF + 2*SMEM_TRE_BYTES)
#define RED_OFF  (X_OFF + SMEM_X_BYTES)
#define SMEM_TOTAL (RED_OFF + 2*SMEM_RED_BYTES)   /* 212992 */

__device__ __forceinline__ uint32_t smem_u32(const void* p) {
    uint32_t a;
    asm("{ .reg .u64 t; cvta.to.shared.u64 t, %1; cvt.u32.u64 %0, t; }"
        : "=r"(a) : "l"(p));
    return a;
}
__device__ __forceinline__ ull pack2(float lo, float hi) {
    ull r; asm("mov.b64 %0, {%1,%2};" : "=l"(r) : "f"(lo), "f"(hi)); return r;
}
__device__ __forceinline__ void fma2(ull& acc, ull a, ull b) {
    asm("fma.rn.f32x2 %0, %1, %2, %0;" : "+l"(acc) : "l"(a), "l"(b));
}
__device__ __forceinline__ float sum2(ull v) {
    float a, b; asm("mov.b64 {%0,%1}, %2;" : "=f"(a), "=f"(b) : "l"(v));
    return a + b;
}
__device__ __forceinline__ ull lds64(uint32_t addr) {
    ull v; asm("ld.shared.b64 %0, [%1];" : "=l"(v) : "r"(addr));
    return v;
}
__device__ __forceinline__ void cp16(uint32_t dst, const void* src) {
    asm volatile("cp.async.cg.shared.global [%0], [%1], 16;"
                 :: "r"(dst), "l"(src));
}
__device__ __forceinline__ void cp_commit() {
    asm volatile("cp.async.commit_group;");
}
__device__ __forceinline__ void cp_wait0() {
    asm volatile("cp.async.wait_group 0;");
}
/* 16B-granularity XOR swizzle: conflict-free for both the coalesced store
   side and the strided per-thread read side. */
__device__ __forceinline__ int swz(int f) { return f ^ ((f >> 3) & 7); }

__global__ void __launch_bounds__(THREADS, 1)
tcq_kernel(const float* __restrict__ inp,
           const int* __restrict__ trellis1,
           const int* __restrict__ trellis2,
           const float* __restrict__ tlut,
           float* __restrict__ out)
{
    extern __shared__ char smem_raw[];
    ull*    lut = (ull*)smem_raw;
    float4* xs  = (float4*)(smem_raw + X_OFF);

    const int tid  = threadIdx.x;
    const int lane = tid & 31;
    const int warp = tid >> 5;
    const int bid  = blockIdx.x;
    const int ko   = tid & 255;     // trellis block within mo
    const int half = tid >> 8;      // 0: word 2tx (cols 0-7), 1: word 2tx+1

    const uint32_t smem_base = smem_u32(smem_raw);
    const uint32_t tre_base  = smem_base + TRE_OFF;
    float* const red0 = (float*)(smem_raw + RED_OFF);
    float* const red1 = (float*)(smem_raw + RED_OFF + SMEM_RED_BYTES);

    const int4* t1v = (const int4*)trellis1;
    const int4* t2v = (const int4*)trellis2;

    // issue trellis prefetch for first block into tre buffer 0 (L1-bypass)
    {
        const int mo = bid;
#pragma unroll
        for (int q = 0; q < 4; q++) {
            const int f = tid + q * THREADS;     // flat 0..2047
            const int4* src = (f < 1024) ? &t1v[(size_t)mo * 1024 + f]
                                         : &t2v[(size_t)mo * 1024 + f - 1024];
            cp16(tre_base + (uint32_t)swz(f) * 16u, src);
        }
        cp_commit();
    }

    // ======== one-time staging (overlapped with the cp.async above) ========
    {   // LUT replicated 16x interleaved: entry e replica r at ull idx e*16+r
        const ull* src = (const ull*)tlut;
#pragma unroll
        for (int k = tid; k < 8192; k += THREADS)
            lut[k] = src[k >> 4];
    }
    {   // x: 4096 float4 flat [b*1024 + c4], swizzled store
        const float4* xv = (const float4*)inp;
#pragma unroll
        for (int f = tid; f < 4096; f += THREADS)
            xs[swz(f)] = xv[f];
    }
    cp_wait0();
    __syncthreads();

    // x for this thread's 8 global columns [ko*16+half*8, +8), 4 batches —
    // constant across all mo blocks.
    ull x2[4][4];
#pragma unroll
    for (int b = 0; b < 4; b++) {
#pragma unroll
        for (int q = 0; q < 2; q++) {
            const int f = b * 1024 + ko * 4 + half * 2 + q;
            const float4 v = xs[swz(f)];
            x2[b][2 * q + 0] = pack2(v.x, v.y);
            x2[b][2 * q + 1] = pack2(v.z, v.w);
        }
    }

    const uint32_t lut_lane = smem_base + (uint32_t)(lane & 15) * 8u;
    // phase rotation offset: the 4 warps of one SMSP (warp%4 = smsp) get
    // distinct offsets -> at any instant they sit in different phases.
    const int off = (warp >> 2) & 3;
    // half-warp value-rotating reduction: lane l ends holding value index
    // bitrev4(l&15), summed over its 16-lane half.
    const int oi = ((lane & 1) << 3) | ((lane & 2) << 1)
                 | ((lane & 4) >> 1) | ((lane & 8) >> 3);
    const int red_slot = warp * 128 + (lane >> 4) * 16 + oi;

#define ROUND(S, N) { _Pragma("unroll")                                   \
        for (int i = 0; i < (N) / 2; i++) {                               \
            const bool hi2 = (lane & (S)) != 0;                           \
            const float snd = hi2 ? v[i] : v[i + (N) / 2];                \
            const float kp  = hi2 ? v[i + (N) / 2] : v[i];                \
            v[i] = kp + __shfl_xor_sync(0xffffffffu, snd, (S));           \
        } }

    // ======== persistent loop: 1 barrier per block, rotated phases ========
    int buf = 0, prev_mo = -1;
    for (int mo = bid; mo < NBLK; mo += NCTA) {
        // prefetch next block's trellis into the other buffer (background)
        const int mon = mo + NCTA;
        if (mon < NBLK) {
            const uint32_t dst = tre_base + (uint32_t)(buf ^ 1) * SMEM_TRE_BYTES;
#pragma unroll
            for (int q = 0; q < 4; q++) {
                const int f = tid + q * THREADS;
                const int4* src = (f < 1024) ? &t1v[(size_t)mon * 1024 + f]
                                             : &t2v[(size_t)mon * 1024 + f - 1024];
                cp16(dst + (uint32_t)swz(f) * 16u, src);
            }
        }
        cp_commit();

        // deferred cross-warp combine for the previous block (other red buf)
        if (prev_mo >= 0 && tid < 64) {
            const float* rp = (buf == 0) ? red1 : red0;
            const int ph = tid >> 4, i = tid & 15;
            float s = 0.f;
#pragma unroll
            for (int w = 0; w < 16; w++)
                s += rp[w * 128 + ph * 32 + i] + rp[w * 128 + ph * 32 + 16 + i];
            const int r = (tid >> 2) & 3;
            const int b = tid & 3;
            out[(size_t)b * OUTF + prev_mo * 16 + ph * 4 + r] = s;
        }

        const int4* tre = (const int4*)(smem_raw + TRE_OFF
                                        + (size_t)buf * SMEM_TRE_BYTES);
        const uint32_t* tre32 = (const uint32_t*)tre;
        float* const red = (buf == 0) ? red0 : red1;

        // Decode: idx[s] = 9-bit window ending at nibble s of the big-endian
        // word stream. half=1 ctx for row tx is p[tx]=(w[2tx]<<16)|w[2tx+1];
        // half=0 ctx is funnel(p[tx], pv, 16), pv low 16 = word[2tx-1].
        // Phases made order-independent by loading pv_in = word[8ph-1]
        // directly (word values < 2^16, upper bits zero in storage).
#pragma unroll
        for (int j = 0; j < 4; j++) {
            const int ph = (j + off) & 3;

            const int4 va = tre[ko * 8 + ((2 * ph)     ^ (ko & 7))];
            const int4 vb = tre[ko * 8 + ((2 * ph + 1) ^ (ko & 7))];
            uint32_t pq[4];
            pq[0] = __byte_perm((uint32_t)va.y, (uint32_t)va.x, 0x5410);
            pq[1] = __byte_perm((uint32_t)va.w, (uint32_t)va.z, 0x5410);
            pq[2] = __byte_perm((uint32_t)vb.y, (uint32_t)vb.x, 0x5410);
            pq[3] = __byte_perm((uint32_t)vb.w, (uint32_t)vb.z, 0x5410);

            uint32_t pv = 0;
            if (half == 0 && ph > 0)
                pv = tre32[(ko * 8 + ((2 * ph - 1) ^ (ko & 7))) * 4 + 3];

            // all 16 gather addresses, then 16 LDS.64 in flight
            ull wv[16];
#pragma unroll
            for (int r = 0; r < 4; r++) {
                const uint32_t ctx = half ? pq[r]
                                          : __funnelshift_l(pq[r], pv, 16);
                pv = pq[r];
#pragma unroll
                for (int t = 0; t < 4; t++)
                    wv[r * 4 + t] = lds64(
                        lut_lane + ((ctx >> (12 - 4 * t)) & 0x1FFu) * 128u);
            }

            ull acc[4][4];
#pragma unroll
            for (int r = 0; r < 4; r++)
#pragma unroll
                for (int b = 0; b < 4; b++) acc[r][b] = 0ull;

#pragma unroll
            for (int r = 0; r < 4; r++)
#pragma unroll
                for (int t = 0; t < 4; t++) {
                    const ull w2 = wv[r * 4 + t];
                    fma2(acc[r][0], w2, x2[0][t]);
                    fma2(acc[r][1], w2, x2[1][t]);
                    fma2(acc[r][2], w2, x2[2][t]);
                    fma2(acc[r][3], w2, x2[3][t]);
                }

            // collapse packed partials; half-warp rotating reduction
            // (4 rounds, S<16: halves reduce independently; both store)
            float v[16];
#pragma unroll
            for (int r = 0; r < 4; r++)
#pragma unroll
                for (int b = 0; b < 4; b++) v[r * 4 + b] = sum2(acc[r][b]);

            ROUND(1, 16) ROUND(2, 8) ROUND(4, 4) ROUND(8, 2)

            red[red_slot + ph * 32] = v[0];
        }

        // single barrier per block: next tre buffer ready + red visible
        cp_wait0();
        __syncthreads();

        prev_mo = mo;
        buf ^= 1;
    }

    // final combine for the last block (red in buf^1 after the flip)
    if (tid < 64) {
        const float* rp = (buf == 0) ? red1 : red0;
        const int ph = tid >> 4, i = tid & 15;
        float s = 0.f;
#pragma unroll
        for (int w = 0; w < 16; w++)
            s += rp[w * 128 + ph * 32 + i] + rp[w * 128 + ph * 32 + 16 + i];
        const int r = (tid >> 2) & 3;
        const int b = tid & 3;
        out[(size_t)b * OUTF + prev_mo * 16 + ph * 4 + r] = s;
    }
#undef ROUND
}

extern "C" void kernel_launch(void* const* d_in, const int* in_sizes, int n_in,
                              void* d_out, int out_size) {
    const float* inp  = (const float*)d_in[0];
    const int*   t1   = (const int*)d_in[1];
    const int*   t2   = (const int*)d_in[2];
    const float* tlut = (const float*)d_in[3];
    float*       out  = (float*)d_out;

    cudaFuncSetAttribute(tcq_kernel,
                         cudaFuncAttributeMaxDynamicSharedMemorySize,
                         SMEM_TOTAL);
    tcq_kernel<<<NCTA, THREADS, SMEM_TOTAL>>>(inp, t1, t2, tlut, out);
}

// round 13
// speedup vs baseline: 1.0618x; 1.0618x over previous
#include <cuda_runtime.h>
#include <cstdint>

typedef unsigned long long ull;

#define THREADS 512
#define OUTF 11008
#define INF 4096
#define NCTA 148                    /* persistent: one CTA per SM */
#define NBLK 688                    /* OUTF/16 row-blocks */

#define SMEM_LUT_BYTES (512*16*8)   /* 64KB: LUT replicated 16x, interleaved  */
#define SMEM_TRE_BYTES (2048*16)    /* 32KB per buffer: 256 blk x 8 int4 swz  */
#define SMEM_X_BYTES   (4096*16)    /* 64KB: x staging, float4 flat, swizzled */
#define SMEM_RED_BYTES (16*128*4)   /* 8KB per buffer (two half-warp slots)   */
#define TRE_OFF  SMEM_LUT_BYTES
#define X_OFF    (TRE_OFF + 2*SMEM_TRE_BYTES)
#define RED_OFF  (X_OFF + SMEM_X_BYTES)
#define SMEM_TOTAL (RED_OFF + 2*SMEM_RED_BYTES)   /* 212992 */

__device__ __forceinline__ uint32_t smem_u32(const void* p) {
    uint32_t a;
    asm("{ .reg .u64 t; cvta.to.shared.u64 t, %1; cvt.u32.u64 %0, t; }"
        : "=r"(a) : "l"(p));
    return a;
}
__device__ __forceinline__ ull pack2(float lo, float hi) {
    ull r; asm("mov.b64 %0, {%1,%2};" : "=l"(r) : "f"(lo), "f"(hi)); return r;
}
__device__ __forceinline__ void fma2(ull& acc, ull a, ull b) {
    asm("fma.rn.f32x2 %0, %1, %2, %0;" : "+l"(acc) : "l"(a), "l"(b));
}
__device__ __forceinline__ ull mul2(ull a, ull b) {   /* rn(a*b), == fma(a,b,0) */
    ull r; asm("mul.rn.f32x2 %0, %1, %2;" : "=l"(r) : "l"(a), "l"(b));
    return r;
}
__device__ __forceinline__ float sum2(ull v) {
    float a, b; asm("mov.b64 {%0,%1}, %2;" : "=f"(a), "=f"(b) : "l"(v));
    return a + b;
}
__device__ __forceinline__ ull lds64(uint32_t addr) {
    ull v; asm("ld.shared.b64 %0, [%1];" : "=l"(v) : "r"(addr));
    return v;
}
__device__ __forceinline__ void cp16(uint32_t dst, const void* src) {
    asm volatile("cp.async.cg.shared.global [%0], [%1], 16;"
                 :: "r"(dst), "l"(src));
}
__device__ __forceinline__ void cp_commit() {
    asm volatile("cp.async.commit_group;");
}
__device__ __forceinline__ void cp_wait0() {
    asm volatile("cp.async.wait_group 0;");
}
/* 16B-granularity XOR swizzle: conflict-free for both the coalesced store
   side and the strided per-thread read side. */
__device__ __forceinline__ int swz(int f) { return f ^ ((f >> 3) & 7); }

__global__ void __launch_bounds__(THREADS, 1)
tcq_kernel(const float* __restrict__ inp,
           const int* __restrict__ trellis1,
           const int* __restrict__ trellis2,
           const float* __restrict__ tlut,
           float* __restrict__ out)
{
    extern __shared__ char smem_raw[];
    ull*    lut = (ull*)smem_raw;
    float4* xs  = (float4*)(smem_raw + X_OFF);

    const int tid  = threadIdx.x;
    const int lane = tid & 31;
    const int warp = tid >> 5;
    const int bid  = blockIdx.x;
    const int ko   = tid & 255;     // trellis block within mo
    const int half = tid >> 8;      // 0: word 2tx (cols 0-7), 1: word 2tx+1

    const uint32_t smem_base = smem_u32(smem_raw);
    const uint32_t tre_base  = smem_base + TRE_OFF;
    float* const red0 = (float*)(smem_raw + RED_OFF);
    float* const red1 = (float*)(smem_raw + RED_OFF + SMEM_RED_BYTES);

    const int4* t1v = (const int4*)trellis1;
    const int4* t2v = (const int4*)trellis2;

    // issue trellis prefetch for first block into tre buffer 0 (L1-bypass)
    {
        const int mo = bid;
#pragma unroll
        for (int q = 0; q < 4; q++) {
            const int f = tid + q * THREADS;     // flat 0..2047
            const int4* src = (f < 1024) ? &t1v[(size_t)mo * 1024 + f]
                                         : &t2v[(size_t)mo * 1024 + f - 1024];
            cp16(tre_base + (uint32_t)swz(f) * 16u, src);
        }
        cp_commit();
    }

    // ======== one-time staging (overlapped with the cp.async above) ========
    {   // LUT replicated 16x interleaved: entry e replica r at ull idx e*16+r
        const ull* src = (const ull*)tlut;
#pragma unroll
        for (int k = tid; k < 8192; k += THREADS)
            lut[k] = src[k >> 4];
    }
    {   // x: 4096 float4 flat [b*1024 + c4], swizzled store
        const float4* xv = (const float4*)inp;
#pragma unroll
        for (int f = tid; f < 4096; f += THREADS)
            xs[swz(f)] = xv[f];
    }
    cp_wait0();
    __syncthreads();

    // x for this thread's 8 global columns [ko*16+half*8, +8), 4 batches —
    // constant across all mo blocks.
    ull x2[4][4];
#pragma unroll
    for (int b = 0; b < 4; b++) {
#pragma unroll
        for (int q = 0; q < 2; q++) {
            const int f = b * 1024 + ko * 4 + half * 2 + q;
            const float4 v = xs[swz(f)];
            x2[b][2 * q + 0] = pack2(v.x, v.y);
            x2[b][2 * q + 1] = pack2(v.z, v.w);
        }
    }

    const uint32_t lut_lane = smem_base + (uint32_t)(lane & 15) * 8u;
    // phase rotation offset: the 4 warps of one SMSP (warp%4 = smsp) get
    // distinct offsets -> at any instant they sit in different phases.
    const int off = (warp >> 2) & 3;
    // half-warp value-rotating reduction: lane l ends holding value index
    // bitrev4(l&15), summed over its 16-lane half.
    const int oi = ((lane & 1) << 3) | ((lane & 2) << 1)
                 | ((lane & 4) >> 1) | ((lane & 8) >> 3);
    const int red_slot = warp * 128 + (lane >> 4) * 16 + oi;

#define ROUND(S, N) { _Pragma("unroll")                                   \
        for (int i = 0; i < (N) / 2; i++) {                               \
            const bool hi2 = (lane & (S)) != 0;                           \
            const float snd = hi2 ? v[i] : v[i + (N) / 2];                \
            const float kp  = hi2 ? v[i + (N) / 2] : v[i];                \
            v[i] = kp + __shfl_xor_sync(0xffffffffu, snd, (S));           \
        } }

    // ======== persistent loop: 1 barrier per block, rotated phases ========
    int buf = 0, prev_mo = -1;
    for (int mo = bid; mo < NBLK; mo += NCTA) {
        // prefetch next block's trellis into the other buffer (background)
        const int mon = mo + NCTA;
        if (mon < NBLK) {
            const uint32_t dst = tre_base + (uint32_t)(buf ^ 1) * SMEM_TRE_BYTES;
#pragma unroll
            for (int q = 0; q < 4; q++) {
                const int f = tid + q * THREADS;
                const int4* src = (f < 1024) ? &t1v[(size_t)mon * 1024 + f]
                                             : &t2v[(size_t)mon * 1024 + f - 1024];
                cp16(dst + (uint32_t)swz(f) * 16u, src);
            }
        }
        cp_commit();

        // deferred cross-warp combine for the previous block (other red buf)
        if (prev_mo >= 0 && tid < 64) {
            const float* rp = (buf == 0) ? red1 : red0;
            const int ph = tid >> 4, i = tid & 15;
            float s = 0.f;
#pragma unroll
            for (int w = 0; w < 16; w++)
                s += rp[w * 128 + ph * 32 + i] + rp[w * 128 + ph * 32 + 16 + i];
            const int r = (tid >> 2) & 3;
            const int b = tid & 3;
            out[(size_t)b * OUTF + prev_mo * 16 + ph * 4 + r] = s;
        }

        const int4* tre = (const int4*)(smem_raw + TRE_OFF
                                        + (size_t)buf * SMEM_TRE_BYTES);
        const uint32_t* tre32 = (const uint32_t*)tre;
        float* const red = (buf == 0) ? red0 : red1;

        // Decode: idx[s] = 9-bit window ending at nibble s of the big-endian
        // word stream. half=1 ctx for row tx is p[tx]=(w[2tx]<<16)|w[2tx+1];
        // half=0 ctx is funnel(p[tx], pv, 16), pv low 16 = word[2tx-1].
        // Phases order-independent: pv_in = word[8ph-1] loaded directly.
#pragma unroll
        for (int j = 0; j < 4; j++) {
            const int ph = (j + off) & 3;

            const int4 va = tre[ko * 8 + ((2 * ph)     ^ (ko & 7))];
            const int4 vb = tre[ko * 8 + ((2 * ph + 1) ^ (ko & 7))];
            uint32_t pq[4];
            pq[0] = __byte_perm((uint32_t)va.y, (uint32_t)va.x, 0x5410);
            pq[1] = __byte_perm((uint32_t)va.w, (uint32_t)va.z, 0x5410);
            pq[2] = __byte_perm((uint32_t)vb.y, (uint32_t)vb.x, 0x5410);
            pq[3] = __byte_perm((uint32_t)vb.w, (uint32_t)vb.z, 0x5410);

            uint32_t pv = 0;
            if (half == 0 && ph > 0)
                pv = tre32[(ko * 8 + ((2 * ph - 1) ^ (ko & 7))) * 4 + 3];

            // all 16 gather addresses, then 16 LDS.64 in flight
            ull wv[16];
#pragma unroll
            for (int r = 0; r < 4; r++) {
                const uint32_t ctx = half ? pq[r]
                                          : __funnelshift_l(pq[r], pv, 16);
                pv = pq[r];
#pragma unroll
                for (int t = 0; t < 4; t++)
                    wv[r * 4 + t] = lds64(
                        lut_lane + ((ctx >> (12 - 4 * t)) & 0x1FFu) * 128u);
            }

            // t=0 initializes acc via MUL (== fma with 0 seed, bit-exact);
            // kills 32 zero-init MOVs per phase.
            ull acc[4][4];
#pragma unroll
            for (int r = 0; r < 4; r++) {
                const ull w0 = wv[r * 4];
                acc[r][0] = mul2(w0, x2[0][0]);
                acc[r][1] = mul2(w0, x2[1][0]);
                acc[r][2] = mul2(w0, x2[2][0]);
                acc[r][3] = mul2(w0, x2[3][0]);
#pragma unroll
                for (int t = 1; t < 4; t++) {
                    const ull w2 = wv[r * 4 + t];
                    fma2(acc[r][0], w2, x2[0][t]);
                    fma2(acc[r][1], w2, x2[1][t]);
                    fma2(acc[r][2], w2, x2[2][t]);
                    fma2(acc[r][3], w2, x2[3][t]);
                }
            }

            // collapse packed partials; half-warp rotating reduction
            // (4 rounds, S<16: halves reduce independently; both store)
            float v[16];
#pragma unroll
            for (int r = 0; r < 4; r++)
#pragma unroll
                for (int b = 0; b < 4; b++) v[r * 4 + b] = sum2(acc[r][b]);

            ROUND(1, 16) ROUND(2, 8) ROUND(4, 4) ROUND(8, 2)

            red[red_slot + ph * 32] = v[0];
        }

        // single barrier per block: next tre buffer ready + red visible
        cp_wait0();
        __syncthreads();

        prev_mo = mo;
        buf ^= 1;
    }

    // final combine for the last block (red in buf^1 after the flip)
    if (tid < 64) {
        const float* rp = (buf == 0) ? red1 : red0;
        const int ph = tid >> 4, i = tid & 15;
        float s = 0.f;
#pragma unroll
        for (int w = 0; w < 16; w++)
            s += rp[w * 128 + ph * 32 + i] + rp[w * 128 + ph * 32 + 16 + i];
        const int r = (tid >> 2) & 3;
        const int b = tid & 3;
        out[(size_t)b * OUTF + prev_mo * 16 + ph * 4 + r] = s;
    }
#undef ROUND
}

extern "C" void kernel_launch(void* const* d_in, const int* in_sizes, int n_in,
                              void* d_out, int out_size) {
    const float* inp  = (const float*)d_in[0];
    const int*   t1   = (const int*)d_in[1];
    const int*   t2   = (const int*)d_in[2];
    const float* tlut = (const float*)d_in[3];
    float*       out  = (float*)d_out;

    cudaFuncSetAttribute(tcq_kernel,
                         cudaFuncAttributeMaxDynamicSharedMemorySize,
                         SMEM_TOTAL);
    tcq_kernel<<<NCTA, THREADS, SMEM_TOTAL>>>(inp, t1, t2, tlut, out);
}

// round 14
// speedup vs baseline: 1.0732x; 1.0107x over previous
#include <cuda_runtime.h>
#include <cstdint>

typedef unsigned long long ull;

#define THREADS 512
#define OUTF 11008
#define NCTA 148                    /* persistent: one CTA per SM */
#define NBLK 688                    /* OUTF/16 row-blocks */

#define LUT_OFF  0                  /* 64KB: LUT replicated 16x, interleaved */
#define TRE_SLOT 32768              /* per-block trellis tile, swizzled      */
#define TRE_OFF  65536              /* 4 slots = 128KB                       */
#define X_OFF    (TRE_OFF + 2*TRE_SLOT)   /* x staging aliases tre slots 2,3 */
#define RED_SLOT 8192               /* 16 warps x 128 floats                 */
#define RED_OFF  (TRE_OFF + 4*TRE_SLOT)   /* 4 slots = 32KB                  */
#define SMEM_TOTAL (RED_OFF + 4*RED_SLOT) /* 229376 */

__device__ __forceinline__ uint32_t smem_u32(const void* p) {
    uint32_t a;
    asm("{ .reg .u64 t; cvta.to.shared.u64 t, %1; cvt.u32.u64 %0, t; }"
        : "=r"(a) : "l"(p));
    return a;
}
__device__ __forceinline__ ull pack2(float lo, float hi) {
    ull r; asm("mov.b64 %0, {%1,%2};" : "=l"(r) : "f"(lo), "f"(hi)); return r;
}
__device__ __forceinline__ void fma2(ull& acc, ull a, ull b) {
    asm("fma.rn.f32x2 %0, %1, %2, %0;" : "+l"(acc) : "l"(a), "l"(b));
}
__device__ __forceinline__ ull mul2(ull a, ull b) {   /* == fma(a,b,0) */
    ull r; asm("mul.rn.f32x2 %0, %1, %2;" : "=l"(r) : "l"(a), "l"(b));
    return r;
}
__device__ __forceinline__ float sum2(ull v) {
    float a, b; asm("mov.b64 {%0,%1}, %2;" : "=f"(a), "=f"(b) : "l"(v));
    return a + b;
}
__device__ __forceinline__ ull lds64(uint32_t addr) {
    ull v; asm("ld.shared.b64 %0, [%1];" : "=l"(v) : "r"(addr));
    return v;
}
__device__ __forceinline__ void cp16(uint32_t dst, const void* src) {
    asm volatile("cp.async.cg.shared.global [%0], [%1], 16;"
                 :: "r"(dst), "l"(src));
}
__device__ __forceinline__ void cp_commit() {
    asm volatile("cp.async.commit_group;");
}
__device__ __forceinline__ void cp_wait0() {
    asm volatile("cp.async.wait_group 0;");
}
/* 16B-granularity XOR swizzle: conflict-free for both the coalesced store
   side and the strided per-thread read side. */
__device__ __forceinline__ int swz(int f) { return f ^ ((f >> 3) & 7); }

#define ROUND(S, N) { _Pragma("unroll")                                   \
    for (int i = 0; i < (N) / 2; i++) {                                   \
        const bool hi2 = (lane & (S)) != 0;                               \
        const float snd = hi2 ? v[i] : v[i + (N) / 2];                    \
        const float kp  = hi2 ? v[i + (N) / 2] : v[i];                    \
        v[i] = kp + __shfl_xor_sync(0xffffffffu, snd, (S));               \
    } }

// One full phase (4 rows) of one block: gather 16 LUT pairs, 64 packed
// FMAs, half-warp value-rotating reduction, store 16 partials.
// Decode: idx[s] = 9-bit window ending at nibble s of the big-endian word
// stream. half=1 ctx for row tx is p[tx]=(w[2tx]<<16)|w[2tx+1]; half=0 ctx
// is funnel(p[tx], pv, 16) with pv chained across this block's phases.
__device__ __forceinline__ void do_phase(
    const int4* __restrict__ tre, float* __restrict__ red,
    uint32_t& pv, const int ph, const int ko, const int half,
    const uint32_t lut_lane, const ull x2[4][4],
    const int lane, const int red_slot)
{
    const int4 va = tre[ko * 8 + ((2 * ph)     ^ (ko & 7))];
    const int4 vb = tre[ko * 8 + ((2 * ph + 1) ^ (ko & 7))];
    uint32_t pq[4];
    pq[0] = __byte_perm((uint32_t)va.y, (uint32_t)va.x, 0x5410);
    pq[1] = __byte_perm((uint32_t)va.w, (uint32_t)va.z, 0x5410);
    pq[2] = __byte_perm((uint32_t)vb.y, (uint32_t)vb.x, 0x5410);
    pq[3] = __byte_perm((uint32_t)vb.w, (uint32_t)vb.z, 0x5410);

    ull wv[16];
#pragma unroll
    for (int r = 0; r < 4; r++) {
        const uint32_t ctx = half ? pq[r] : __funnelshift_l(pq[r], pv, 16);
        pv = pq[r];
#pragma unroll
        for (int t = 0; t < 4; t++)
            wv[r * 4 + t] = lds64(
                lut_lane + ((ctx >> (12 - 4 * t)) & 0x1FFu) * 128u);
    }

    ull acc[4][4];
#pragma unroll
    for (int r = 0; r < 4; r++) {
        const ull w0 = wv[r * 4];
        acc[r][0] = mul2(w0, x2[0][0]);
        acc[r][1] = mul2(w0, x2[1][0]);
        acc[r][2] = mul2(w0, x2[2][0]);
        acc[r][3] = mul2(w0, x2[3][0]);
#pragma unroll
        for (int t = 1; t < 4; t++) {
            const ull w2 = wv[r * 4 + t];
            fma2(acc[r][0], w2, x2[0][t]);
            fma2(acc[r][1], w2, x2[1][t]);
            fma2(acc[r][2], w2, x2[2][t]);
            fma2(acc[r][3], w2, x2[3][t]);
        }
    }

    float v[16];
#pragma unroll
    for (int r = 0; r < 4; r++)
#pragma unroll
        for (int b = 0; b < 4; b++) v[r * 4 + b] = sum2(acc[r][b]);

    ROUND(1, 16) ROUND(2, 8) ROUND(4, 4) ROUND(8, 2)

    red[red_slot + ph * 32] = v[0];
}

__global__ void __launch_bounds__(THREADS, 1)
tcq_kernel(const float* __restrict__ inp,
           const int* __restrict__ trellis1,
           const int* __restrict__ trellis2,
           const float* __restrict__ tlut,
           float* __restrict__ out)
{
    extern __shared__ char smem_raw[];
    ull*    lut = (ull*)smem_raw;
    float4* xs  = (float4*)(smem_raw + X_OFF);

    const int tid  = threadIdx.x;
    const int lane = tid & 31;
    const int warp = tid >> 5;
    const int bid  = blockIdx.x;
    const int ko   = tid & 255;
    const int half = tid >> 8;

    const uint32_t smem_base = smem_u32(smem_raw);
    const uint32_t tre_base  = smem_base + TRE_OFF;
    const int4* t1v = (const int4*)trellis1;
    const int4* t2v = (const int4*)trellis2;

#define PREFETCH(MO, SLOTBASE) {                                          \
    _Pragma("unroll")                                                     \
    for (int q = 0; q < 4; q++) {                                         \
        const int f = tid + q * THREADS;                                  \
        const int4* src = (f < 1024)                                      \
            ? &t1v[(size_t)(MO) * 1024 + f]                               \
            : &t2v[(size_t)(MO) * 1024 + f - 1024];                       \
        cp16((SLOTBASE) + (uint32_t)swz(f) * 16u, src);                   \
    } }

    // prefetch pair 0 into tre slots 0,1 (every CTA has >= 2 blocks)
    PREFETCH(bid, tre_base)
    PREFETCH(bid + NCTA, tre_base + TRE_SLOT)
    cp_commit();

    // one-time staging (overlapped with the cp.async above)
    {   // LUT replicated 16x interleaved: entry e replica r at ull idx e*16+r
        const ull* src = (const ull*)tlut;
#pragma unroll
        for (int k = tid; k < 8192; k += THREADS)
            lut[k] = src[k >> 4];
    }
    {   // x: 4096 float4 flat [b*1024 + c4], swizzled (region = tre slots 2,3)
        const float4* xv = (const float4*)inp;
#pragma unroll
        for (int f = tid; f < 4096; f += THREADS)
            xs[swz(f)] = xv[f];
    }
    cp_wait0();
    __syncthreads();

    // x for this thread's 8 global columns, 4 batches — constant all blocks
    ull x2[4][4];
#pragma unroll
    for (int b = 0; b < 4; b++) {
#pragma unroll
        for (int q = 0; q < 2; q++) {
            const int f = b * 1024 + ko * 4 + half * 2 + q;
            const float4 v = xs[swz(f)];
            x2[b][2 * q + 0] = pack2(v.x, v.y);
            x2[b][2 * q + 1] = pack2(v.z, v.w);
        }
    }
    __syncthreads();    // xs region dead only after ALL threads read it

    const uint32_t lut_lane = smem_base + (uint32_t)(lane & 15) * 8u;
    const int oi = ((lane & 1) << 3) | ((lane & 2) << 1)
                 | ((lane & 4) >> 1) | ((lane & 8) >> 3);
    const int red_slot = warp * 128 + (lane >> 4) * 16 + oi;
    float* const red_all = (float*)(smem_raw + RED_OFF);

#define COMBINE(PM0, PM1, PARITY) {                                       \
    if ((PM0) >= 0 && tid < 128) {                                        \
        const int blk  = tid >> 6;                                        \
        const int mo_t = blk ? (PM1) : (PM0);                             \
        if (mo_t >= 0) {                                                  \
            const float* r = red_all + (PARITY) * 4096 + blk * 2048;      \
            const int j = tid & 63;                                       \
            const int phx = j >> 4, ii = j & 15;                          \
            float s = 0.f;                                                \
            _Pragma("unroll")                                             \
            for (int w = 0; w < 16; w++)                                  \
                s += r[w * 128 + phx * 32 + ii]                           \
                   + r[w * 128 + phx * 32 + 16 + ii];                     \
            out[(size_t)(j & 3) * OUTF + mo_t * 16 + phx * 4              \
                + ((j >> 2) & 3)] = s;                                    \
        }                                                                 \
    } }

    // ======== pair loop: ONE barrier per 2 blocks, phases interleaved ====
    int pr = 0, pm0 = -1, pm1 = -1;
    for (int mo = bid; mo < NBLK; mo += 2 * NCTA) {
        const int moB = mo + NCTA;
        const bool haveB = (moB < NBLK);

        // prefetch next pair into the other parity's tre slots
        {
            const int n0 = mo + 2 * NCTA;
            const int n1 = n0 + NCTA;
            const uint32_t s0 = tre_base + (uint32_t)(pr ^ 1) * 2u * TRE_SLOT;
            if (n0 < NBLK) PREFETCH(n0, s0)
            if (n1 < NBLK) PREFETCH(n1, s0 + TRE_SLOT)
            cp_commit();
        }

        // deferred combine for the previous pair (other red parity)
        COMBINE(pm0, pm1, pr ^ 1)

        const int4* treA = (const int4*)(smem_raw + TRE_OFF
                                         + (size_t)pr * 2 * TRE_SLOT);
        const int4* treB = (const int4*)((const char*)treA + TRE_SLOT);
        float* const redA = red_all + pr * 4096;
        float* const redB = redA + 2048;

        uint32_t pvA = 0, pvB = 0;
        if (haveB) {
            // interleaved: B's gathers overlap A's serial SHFL chain
#pragma unroll
            for (int ph = 0; ph < 4; ph++) {
                do_phase(treA, redA, pvA, ph, ko, half, lut_lane, x2, lane, red_slot);
                do_phase(treB, redB, pvB, ph, ko, half, lut_lane, x2, lane, red_slot);
            }
        } else {
#pragma unroll
            for (int ph = 0; ph < 4; ph++)
                do_phase(treA, redA, pvA, ph, ko, half, lut_lane, x2, lane, red_slot);
        }

        cp_wait0();
        __syncthreads();

        pm0 = mo;
        pm1 = haveB ? moB : -1;
        pr ^= 1;
    }

    // final combine for the last pair (its red parity = pr^1 after the flip)
    COMBINE(pm0, pm1, pr ^ 1)

#undef COMBINE
#undef PREFETCH
}

extern "C" void kernel_launch(void* const* d_in, const int* in_sizes, int n_in,
                              void* d_out, int out_size) {
    const float* inp  = (const float*)d_in[0];
    const int*   t1   = (const int*)d_in[1];
    const int*   t2   = (const int*)d_in[2];
    const float* tlut = (const float*)d_in[3];
    float*       out  = (float*)d_out;

    cudaFuncSetAttribute(tcq_kernel,
                         cudaFuncAttributeMaxDynamicSharedMemorySize,
                         SMEM_TOTAL);
    tcq_kernel<<<NCTA, THREADS, SMEM_TOTAL>>>(inp, t1, t2, tlut, out);
}